// round 12
// baseline (speedup 1.0000x reference)
#include <cuda_runtime.h>
#include <cstdint>

// WaveNet dilated causal conv stack.
// 2-CTA cluster per batch element; fused conv+io; ping-pong h in SMEM.
// 2 positions/thread (float2), NTH=544 one-shot bodies (R5 champion body).
// Scalar constant weights (uniform path). POST-BODY push halo exchange.
// Layer loop NOT unrolled (I$ footprint). Split: M0=1088; M_i = 1086 + 2^(i+1).

#define NTH 544
#define LBUF 2176
#define FRAME 128
#define TFULL 4096

typedef unsigned long long u64;

#define OC0   0
#define OCK   24      // [(i-1)*3+w][ci][co]
#define OCB   1752    // [i][co]
#define OIOK  1832    // [i][ci][co]
#define OIOB  2408    // [i][co]
#define OMIX  2480    // [i][co]
#define OMIXB 2560
#define NW    2561

__constant__ float Wc[NW];
__device__ float Wstage[NW];

__device__ __forceinline__ uint32_t s2u(const void* p) {
    return (uint32_t)__cvta_generic_to_shared(p);
}
__device__ __forceinline__ uint32_t mapa_peer(uint32_t a, uint32_t peer) {
    uint32_t r;
    asm volatile("mapa.shared::cluster.u32 %0, %1, %2;" : "=r"(r) : "r"(a), "r"(peer));
    return r;
}
__device__ __forceinline__ void st_dsm64(uint32_t a, float x, float y) {
    u64 v = (u64)__float_as_uint(x) | ((u64)__float_as_uint(y) << 32);
    asm volatile("st.shared::cluster.b64 [%0], %1;" :: "r"(a), "l"(v) : "memory");
}
#define CS() do { asm volatile("barrier.cluster.arrive.aligned;" ::: "memory"); \
                  asm volatile("barrier.cluster.wait.aligned;" ::: "memory"); } while(0)

__global__ void pack_weights(const float* __restrict__ c0,  const float* __restrict__ ck,
                             const float* __restrict__ cb,  const float* __restrict__ iok,
                             const float* __restrict__ iob, const float* __restrict__ mix,
                             const float* __restrict__ mixb) {
    int i = blockIdx.x * blockDim.x + threadIdx.x;
    if (i >= NW) return;
    float v;
    if      (i < OCK)   v = c0[i - OC0];
    else if (i < OCB)   v = ck[i - OCK];
    else if (i < OIOK)  v = cb[i - OCB];
    else if (i < OIOB)  v = iok[i - OIOK];
    else if (i < OMIX)  v = iob[i - OIOB];
    else if (i < OMIXB) v = mix[i - OMIX];
    else                v = mixb[0];
    Wstage[i] = v;
}

extern __shared__ float smem[];

__global__ __launch_bounds__(NTH) __cluster_dims__(2, 1, 1)
void wavenet_kernel(const float* __restrict__ X, float* __restrict__ out)
{
    float* xb   = smem;              // LBUF
    float* hA   = smem + LBUF;       // 8*LBUF   h[c*LBUF + l]
    float* hB   = smem + 9 * LBUF;   // 8*LBUF
    float* oacc = smem + 17 * LBUF;  // FRAME

    const int tid = threadIdx.x;
    uint32_t rank;
    asm("mov.u32 %0, %%cluster_ctarank;" : "=r"(rank));
    const uint32_t peer = rank ^ 1u;
    const int b = blockIdx.x >> 1;
    const float* x = X + b * TFULL + (TFULL - LBUF);

    for (int l = tid; l < LBUF; l += NTH) xb[l] = x[l];
    if (rank && tid < FRAME) oacc[tid] = Wc[OMIXB];
    __syncthreads();

    // ---- layer 0 (pairs) -> hA ----
    {
        const int M = 1088;
        const int lo = rank ? M : 2;
        const int hi = rank ? LBUF : M;
        for (int l = lo + 2 * tid; l < hi; l += 2 * NTH) {
            float2 A = *(const float2*)&xb[l - 2];
            float2 B = *(const float2*)&xb[l];
            float acc0[8], acc1[8];
#pragma unroll
            for (int co = 0; co < 8; co++) {
                float w0 = Wc[OC0 + co], w1 = Wc[OC0 + 8 + co], w2 = Wc[OC0 + 16 + co];
                float bb = Wc[OCB + co];
                acc0[co] = fmaxf(fmaf(B.x, w2, fmaf(A.y, w1, fmaf(A.x, w0, bb))), 0.0f);
                acc1[co] = fmaxf(fmaf(B.y, w2, fmaf(B.x, w1, fmaf(A.y, w0, bb))), 0.0f);
            }
            if (l >= LBUF - FRAME) {
                float m0 = 0.0f, m1 = 0.0f;
#pragma unroll
                for (int co = 0; co < 8; co++) {
                    float mw = Wc[OMIX + co];
                    m0 = fmaf(acc0[co], mw, m0); m1 = fmaf(acc1[co], mw, m1);
                }
                oacc[l - (LBUF - FRAME)]     += m0;
                oacc[l - (LBUF - FRAME) + 1] += m1;
            }
#pragma unroll
            for (int co = 0; co < 8; co++) {
                float bb = Wc[OIOB + co];
                float a0 = bb + B.x, a1 = bb + B.y;
#pragma unroll
                for (int ci = 0; ci < 8; ci++) {
                    float wk = Wc[OIOK + ci * 8 + co];
                    a0 = fmaf(acc0[ci], wk, a0); a1 = fmaf(acc1[ci], wk, a1);
                }
                *(float2*)(hA + co * LBUF + l) = make_float2(a0, a1);
            }
        }
        __syncthreads();
        // push layer-0 boundary: rank0 [1086,1088), rank1 [1088,1090)  (1 pair per ci)
        {
            const int base = rank ? 1088 : 1086;
            const uint32_t pb = mapa_peer(s2u(hA), peer);
            if (tid < 8) {
                const int idx = tid * LBUF + base;
                float2 v = *(const float2*)(hA + idx);
                st_dsm64(pb + (uint32_t)idx * 4u, v.x, v.y);
            }
        }
    }
    CS();

    // ---- layers 1..8 (pairs), ping-pong, post-body push halos ----
#pragma unroll 1
    for (int i = 1; i < 9; i++) {
        const int d = 1 << i;
        const int S = (4 << i) - 2;            // 2*(2^{i+1}-1)
        const int M = 1086 + (2 << i);
        float* cur = (i & 1) ? hA : hB;
        float* nxt = (i & 1) ? hB : hA;

        const int lo = rank ? M : S;
        const int hi = rank ? LBUF : M;
        for (int l = lo + 2 * tid; l < hi; l += 2 * NTH) {
            float acc0[8], acc1[8], hl0[8], hl1[8];
#pragma unroll
            for (int co = 0; co < 8; co++) { acc0[co] = Wc[OCB + i * 8 + co]; acc1[co] = acc0[co]; }
#pragma unroll
            for (int w = 0; w < 3; w++) {
                const int off = (2 - w) * d;
#pragma unroll
                for (int ci = 0; ci < 8; ci++) {
                    float2 v = *(const float2*)(cur + ci * LBUF + (l - off));
                    if (w == 2) { hl0[ci] = v.x; hl1[ci] = v.y; }
#pragma unroll
                    for (int co = 0; co < 8; co++) {
                        float wk = Wc[OCK + (((i - 1) * 3 + w) * 8 + ci) * 8 + co];
                        acc0[co] = fmaf(v.x, wk, acc0[co]); acc1[co] = fmaf(v.y, wk, acc1[co]);
                    }
                }
            }
#pragma unroll
            for (int co = 0; co < 8; co++) { acc0[co] = fmaxf(acc0[co], 0.0f); acc1[co] = fmaxf(acc1[co], 0.0f); }
            if (l >= LBUF - FRAME) {
                float m0 = 0.0f, m1 = 0.0f;
#pragma unroll
                for (int co = 0; co < 8; co++) {
                    float mw = Wc[OMIX + i * 8 + co];
                    m0 = fmaf(acc0[co], mw, m0); m1 = fmaf(acc1[co], mw, m1);
                }
                oacc[l - (LBUF - FRAME)]     += m0;
                oacc[l - (LBUF - FRAME) + 1] += m1;
            }
#pragma unroll
            for (int co = 0; co < 8; co++) {
                float bb = Wc[OIOB + i * 8 + co];
                float a0 = bb + hl0[co], a1 = bb + hl1[co];
#pragma unroll
                for (int ci = 0; ci < 8; ci++) {
                    float wk = Wc[OIOK + (i * 8 + ci) * 8 + co];
                    a0 = fmaf(acc0[ci], wk, a0); a1 = fmaf(acc1[ci], wk, a1);
                }
                *(float2*)(nxt + co * LBUF + l) = make_float2(a0, a1);
            }
        }
        __syncthreads();

        // push layer-i output halo (consumed by layer i+1)
        const uint32_t pb = mapa_peer(s2u(nxt), peer);
        if (i < 8) {
            const int W  = 2 << i;                 // 2^{i+1}
            const int Wp = W >> 1;                 // pairs
            const int base = rank ? M : (M - W);   // rank0: [1086, M); rank1: [M, M+W)
            for (int e = tid; e < 8 * Wp; e += NTH) {
                const int ci = e / Wp, j = e - ci * Wp;
                const int idx = ci * LBUF + base + 2 * j;
                float2 v = *(const float2*)(nxt + idx);
                st_dsm64(pb + (uint32_t)idx * 4u, v.x, v.y);
            }
        } else if (!rank) {
            // layer-9 runs on rank1 only; rank0 pushes strips [1024,1152) and [1536,1598)
            for (int e = tid; e < 8 * 64; e += NTH) {          // 64 pairs per ci
                const int ci = e >> 6, j = e & 63;
                const int idx = ci * LBUF + 1024 + 2 * j;
                float2 v = *(const float2*)(nxt + idx);
                st_dsm64(pb + (uint32_t)idx * 4u, v.x, v.y);
            }
            for (int e = tid; e < 8 * 31; e += NTH) {          // 31 pairs per ci
                const int ci = e / 31, j = e - ci * 31;
                const int idx = ci * LBUF + 1536 + 2 * j;
                float2 v = *(const float2*)(nxt + idx);
                st_dsm64(pb + (uint32_t)idx * 4u, v.x, v.y);
            }
        }
        CS();
    }

    // ---- layer 9 (rank1 only, pairs): reads own hA, last FRAME positions ----
    if (rank) {
        const int i = 9, d = 512;
        for (int l = (LBUF - FRAME) + 2 * tid; l < LBUF; l += 2 * NTH) {
            float acc0[8], acc1[8];
#pragma unroll
            for (int co = 0; co < 8; co++) { acc0[co] = Wc[OCB + i * 8 + co]; acc1[co] = acc0[co]; }
#pragma unroll
            for (int w = 0; w < 3; w++) {
                const int off = (2 - w) * d;
#pragma unroll
                for (int ci = 0; ci < 8; ci++) {
                    float2 v = *(const float2*)(hA + ci * LBUF + (l - off));
#pragma unroll
                    for (int co = 0; co < 8; co++) {
                        float wk = Wc[OCK + (((i - 1) * 3 + w) * 8 + ci) * 8 + co];
                        acc0[co] = fmaf(v.x, wk, acc0[co]); acc1[co] = fmaf(v.y, wk, acc1[co]);
                    }
                }
            }
            float m0 = 0.0f, m1 = 0.0f;
#pragma unroll
            for (int co = 0; co < 8; co++) {
                float mw = Wc[OMIX + i * 8 + co];
                m0 = fmaf(fmaxf(acc0[co], 0.0f), mw, m0);
                m1 = fmaf(fmaxf(acc1[co], 0.0f), mw, m1);
            }
            oacc[l - (LBUF - FRAME)]     += m0;
            oacc[l - (LBUF - FRAME) + 1] += m1;
        }
        __syncthreads();
        if (tid < FRAME) out[b * FRAME + tid] = oacc[tid];
    }
}

static const int SMEM_BYTES = (17 * LBUF + FRAME) * (int)sizeof(float);

extern "C" void kernel_launch(void* const* d_in, const int* in_sizes, int n_in,
                              void* d_out, int out_size) {
    (void)in_sizes; (void)n_in; (void)out_size;
    cudaFuncSetAttribute(wavenet_kernel, cudaFuncAttributeMaxDynamicSharedMemorySize, SMEM_BYTES);

    pack_weights<<<(NW + 511) / 512, 512>>>(
        (const float*)d_in[1], (const float*)d_in[2], (const float*)d_in[3],
        (const float*)d_in[4], (const float*)d_in[5], (const float*)d_in[6],
        (const float*)d_in[7]);

    void* wp = nullptr;
    cudaGetSymbolAddress(&wp, Wstage);
    cudaMemcpyToSymbolAsync(Wc, wp, NW * sizeof(float), 0, cudaMemcpyDeviceToDevice, 0);

    wavenet_kernel<<<128, NTH, SMEM_BYTES>>>((const float*)d_in[0], (float*)d_out);
}

// round 13
// speedup vs baseline: 1.4942x; 1.4942x over previous
#include <cuda_runtime.h>
#include <cstdint>

// WaveNet dilated causal conv stack.
// 2-CTA cluster per batch element; fused conv+io; ping-pong h in SMEM.
// 2 positions/thread (float2), NTH=544 one-shot bodies (R5 champion body).
// Scalar constant weights (uniform path). FULLY UNROLLED layer loop.
// Single change vs R5: pull halos -> post-body push halos (R10-verified windows).
// Split points: M0=1088; M_i = 1086 + 2^(i+1).

#define NTH 544
#define LBUF 2176
#define FRAME 128
#define TFULL 4096

typedef unsigned long long u64;

#define OC0   0
#define OCK   24      // [(i-1)*3+w][ci][co]
#define OCB   1752    // [i][co]
#define OIOK  1832    // [i][ci][co]
#define OIOB  2408    // [i][co]
#define OMIX  2480    // [i][co]
#define OMIXB 2560
#define NW    2561

__constant__ float Wc[NW];
__device__ float Wstage[NW];

__device__ __forceinline__ uint32_t s2u(const void* p) {
    return (uint32_t)__cvta_generic_to_shared(p);
}
__device__ __forceinline__ uint32_t mapa_peer(uint32_t a, uint32_t peer) {
    uint32_t r;
    asm volatile("mapa.shared::cluster.u32 %0, %1, %2;" : "=r"(r) : "r"(a), "r"(peer));
    return r;
}
__device__ __forceinline__ void st_dsm64(uint32_t a, float x, float y) {
    u64 v = (u64)__float_as_uint(x) | ((u64)__float_as_uint(y) << 32);
    asm volatile("st.shared::cluster.b64 [%0], %1;" :: "r"(a), "l"(v) : "memory");
}
#define CS() do { asm volatile("barrier.cluster.arrive.aligned;" ::: "memory"); \
                  asm volatile("barrier.cluster.wait.aligned;" ::: "memory"); } while(0)

__global__ void pack_weights(const float* __restrict__ c0,  const float* __restrict__ ck,
                             const float* __restrict__ cb,  const float* __restrict__ iok,
                             const float* __restrict__ iob, const float* __restrict__ mix,
                             const float* __restrict__ mixb) {
    int i = blockIdx.x * blockDim.x + threadIdx.x;
    if (i >= NW) return;
    float v;
    if      (i < OCK)   v = c0[i - OC0];
    else if (i < OCB)   v = ck[i - OCK];
    else if (i < OIOK)  v = cb[i - OCB];
    else if (i < OIOB)  v = iok[i - OIOK];
    else if (i < OMIX)  v = iob[i - OIOB];
    else if (i < OMIXB) v = mix[i - OMIX];
    else                v = mixb[0];
    Wstage[i] = v;
}

extern __shared__ float smem[];

__global__ __launch_bounds__(NTH) __cluster_dims__(2, 1, 1)
void wavenet_kernel(const float* __restrict__ X, float* __restrict__ out)
{
    float* xb   = smem;              // LBUF
    float* hA   = smem + LBUF;       // 8*LBUF   h[c*LBUF + l]
    float* hB   = smem + 9 * LBUF;   // 8*LBUF
    float* oacc = smem + 17 * LBUF;  // FRAME

    const int tid = threadIdx.x;
    uint32_t rank;
    asm("mov.u32 %0, %%cluster_ctarank;" : "=r"(rank));
    const uint32_t peer = rank ^ 1u;
    const int b = blockIdx.x >> 1;
    const float* x = X + b * TFULL + (TFULL - LBUF);

    for (int l = tid; l < LBUF; l += NTH) xb[l] = x[l];
    if (rank && tid < FRAME) oacc[tid] = Wc[OMIXB];
    __syncthreads();

    // ---- layer 0 (pairs) -> hA; then push boundary pair ----
    {
        const int M = 1088;
        const int lo = rank ? M : 2;
        const int hi = rank ? LBUF : M;
        for (int l = lo + 2 * tid; l < hi; l += 2 * NTH) {
            float2 A = *(const float2*)&xb[l - 2];
            float2 B = *(const float2*)&xb[l];
            float acc0[8], acc1[8];
#pragma unroll
            for (int co = 0; co < 8; co++) {
                float w0 = Wc[OC0 + co], w1 = Wc[OC0 + 8 + co], w2 = Wc[OC0 + 16 + co];
                float bb = Wc[OCB + co];
                acc0[co] = fmaxf(fmaf(B.x, w2, fmaf(A.y, w1, fmaf(A.x, w0, bb))), 0.0f);
                acc1[co] = fmaxf(fmaf(B.y, w2, fmaf(B.x, w1, fmaf(A.y, w0, bb))), 0.0f);
            }
            if (l >= LBUF - FRAME) {
                float m0 = 0.0f, m1 = 0.0f;
#pragma unroll
                for (int co = 0; co < 8; co++) {
                    float mw = Wc[OMIX + co];
                    m0 = fmaf(acc0[co], mw, m0); m1 = fmaf(acc1[co], mw, m1);
                }
                oacc[l - (LBUF - FRAME)]     += m0;
                oacc[l - (LBUF - FRAME) + 1] += m1;
            }
#pragma unroll
            for (int co = 0; co < 8; co++) {
                float bb = Wc[OIOB + co];
                float a0 = bb + B.x, a1 = bb + B.y;
#pragma unroll
                for (int ci = 0; ci < 8; ci++) {
                    float wk = Wc[OIOK + ci * 8 + co];
                    a0 = fmaf(acc0[ci], wk, a0); a1 = fmaf(acc1[ci], wk, a1);
                }
                *(float2*)(hA + co * LBUF + l) = make_float2(a0, a1);
            }
        }
        __syncthreads();
        // layer-1 halo (d=2): rank0 pushes [1086,1088), rank1 pushes [1088,1090)
        const int base = rank ? 1088 : 1086;
        const uint32_t pb = mapa_peer(s2u(hA), peer);
        if (tid < 8) {
            const int idx = tid * LBUF + base;
            float2 v = *(const float2*)(hA + idx);
            st_dsm64(pb + (uint32_t)idx * 4u, v.x, v.y);
        }
    }
    CS();

    // ---- layers 1..8 (pairs), ping-pong, post-body push halos ----
#pragma unroll
    for (int i = 1; i < 9; i++) {
        const int d = 1 << i;
        const int S = (4 << i) - 2;            // 2*(2^{i+1}-1)
        const int M = 1086 + (2 << i);
        float* cur = (i & 1) ? hA : hB;
        float* nxt = (i & 1) ? hB : hA;

        const int lo = rank ? M : S;
        const int hi = rank ? LBUF : M;
        for (int l = lo + 2 * tid; l < hi; l += 2 * NTH) {
            float acc0[8], acc1[8], hl0[8], hl1[8];
#pragma unroll
            for (int co = 0; co < 8; co++) { acc0[co] = Wc[OCB + i * 8 + co]; acc1[co] = acc0[co]; }
#pragma unroll
            for (int w = 0; w < 3; w++) {
                const int off = (2 - w) * d;
#pragma unroll
                for (int ci = 0; ci < 8; ci++) {
                    float2 v = *(const float2*)(cur + ci * LBUF + (l - off));
                    if (w == 2) { hl0[ci] = v.x; hl1[ci] = v.y; }
#pragma unroll
                    for (int co = 0; co < 8; co++) {
                        float wk = Wc[OCK + (((i - 1) * 3 + w) * 8 + ci) * 8 + co];
                        acc0[co] = fmaf(v.x, wk, acc0[co]); acc1[co] = fmaf(v.y, wk, acc1[co]);
                    }
                }
            }
#pragma unroll
            for (int co = 0; co < 8; co++) { acc0[co] = fmaxf(acc0[co], 0.0f); acc1[co] = fmaxf(acc1[co], 0.0f); }
            if (l >= LBUF - FRAME) {
                float m0 = 0.0f, m1 = 0.0f;
#pragma unroll
                for (int co = 0; co < 8; co++) {
                    float mw = Wc[OMIX + i * 8 + co];
                    m0 = fmaf(acc0[co], mw, m0); m1 = fmaf(acc1[co], mw, m1);
                }
                oacc[l - (LBUF - FRAME)]     += m0;
                oacc[l - (LBUF - FRAME) + 1] += m1;
            }
#pragma unroll
            for (int co = 0; co < 8; co++) {
                float bb = Wc[OIOB + i * 8 + co];
                float a0 = bb + hl0[co], a1 = bb + hl1[co];
#pragma unroll
                for (int ci = 0; ci < 8; ci++) {
                    float wk = Wc[OIOK + (i * 8 + ci) * 8 + co];
                    a0 = fmaf(acc0[ci], wk, a0); a1 = fmaf(acc1[ci], wk, a1);
                }
                *(float2*)(nxt + co * LBUF + l) = make_float2(a0, a1);
            }
        }
        __syncthreads();

        // push layer-i output halo (consumed by layer i+1)
        const uint32_t pb = mapa_peer(s2u(nxt), peer);
        if (i < 8) {
            const int W  = 2 << i;                 // 2^{i+1}
            const int Wp = W >> 1;                 // pairs
            const int base = rank ? M : (M - W);   // rank0: [1086, M); rank1: [M, M+W)
            for (int e = tid; e < 8 * Wp; e += NTH) {
                const int ci = e / Wp, j = e - ci * Wp;
                const int idx = ci * LBUF + base + 2 * j;
                float2 v = *(const float2*)(nxt + idx);
                st_dsm64(pb + (uint32_t)idx * 4u, v.x, v.y);
            }
        } else if (!rank) {
            // layer-9 runs on rank1 only; rank0 pushes strips [1024,1152) and [1536,1598)
            for (int e = tid; e < 8 * 64; e += NTH) {          // 64 pairs per ci
                const int ci = e >> 6, j = e & 63;
                const int idx = ci * LBUF + 1024 + 2 * j;
                float2 v = *(const float2*)(nxt + idx);
                st_dsm64(pb + (uint32_t)idx * 4u, v.x, v.y);
            }
            for (int e = tid; e < 8 * 31; e += NTH) {          // 31 pairs per ci
                const int ci = e / 31, j = e - ci * 31;
                const int idx = ci * LBUF + 1536 + 2 * j;
                float2 v = *(const float2*)(nxt + idx);
                st_dsm64(pb + (uint32_t)idx * 4u, v.x, v.y);
            }
        }
        CS();
    }

    // ---- layer 9 (rank1 only, pairs): reads own hA, last FRAME positions ----
    if (rank) {
        const int i = 9, d = 512;
        for (int l = (LBUF - FRAME) + 2 * tid; l < LBUF; l += 2 * NTH) {
            float acc0[8], acc1[8];
#pragma unroll
            for (int co = 0; co < 8; co++) { acc0[co] = Wc[OCB + i * 8 + co]; acc1[co] = acc0[co]; }
#pragma unroll
            for (int w = 0; w < 3; w++) {
                const int off = (2 - w) * d;
#pragma unroll
                for (int ci = 0; ci < 8; ci++) {
                    float2 v = *(const float2*)(hA + ci * LBUF + (l - off));
#pragma unroll
                    for (int co = 0; co < 8; co++) {
                        float wk = Wc[OCK + (((i - 1) * 3 + w) * 8 + ci) * 8 + co];
                        acc0[co] = fmaf(v.x, wk, acc0[co]); acc1[co] = fmaf(v.y, wk, acc1[co]);
                    }
                }
            }
            float m0 = 0.0f, m1 = 0.0f;
#pragma unroll
            for (int co = 0; co < 8; co++) {
                float mw = Wc[OMIX + i * 8 + co];
                m0 = fmaf(fmaxf(acc0[co], 0.0f), mw, m0);
                m1 = fmaf(fmaxf(acc1[co], 0.0f), mw, m1);
            }
            oacc[l - (LBUF - FRAME)]     += m0;
            oacc[l - (LBUF - FRAME) + 1] += m1;
        }
        __syncthreads();
        if (tid < FRAME) out[b * FRAME + tid] = oacc[tid];
    }
}

static const int SMEM_BYTES = (17 * LBUF + FRAME) * (int)sizeof(float);

extern "C" void kernel_launch(void* const* d_in, const int* in_sizes, int n_in,
                              void* d_out, int out_size) {
    (void)in_sizes; (void)n_in; (void)out_size;
    cudaFuncSetAttribute(wavenet_kernel, cudaFuncAttributeMaxDynamicSharedMemorySize, SMEM_BYTES);

    pack_weights<<<(NW + 511) / 512, 512>>>(
        (const float*)d_in[1], (const float*)d_in[2], (const float*)d_in[3],
        (const float*)d_in[4], (const float*)d_in[5], (const float*)d_in[6],
        (const float*)d_in[7]);

    void* wp = nullptr;
    cudaGetSymbolAddress(&wp, Wstage);
    cudaMemcpyToSymbolAsync(Wc, wp, NW * sizeof(float), 0, cudaMemcpyDeviceToDevice, 0);

    wavenet_kernel<<<128, NTH, SMEM_BYTES>>>((const float*)d_in[0], (float*)d_out);
}

// round 14
// speedup vs baseline: 1.5200x; 1.0173x over previous
#include <cuda_runtime.h>
#include <cstdint>

// WaveNet dilated causal conv stack.
// 2-CTA cluster per batch element; fused conv+io; ping-pong h in SMEM.
// 2 positions/thread (float2), NTH=544 one-shot bodies.
// Scalar constant weights (uniform path). Producer pushes halo pairs straight
// from registers in a predicated tail; no __syncthreads in the layer loop
// (cluster barrier orders both own-CTA SMEM and pushed halos).
// Split points: M0=1088; M_i = 1086 + 2^(i+1)  (R13-verified geometry).

#define NTH 544
#define LBUF 2176
#define FRAME 128
#define TFULL 4096

typedef unsigned long long u64;

#define OC0   0
#define OCK   24      // [(i-1)*3+w][ci][co]
#define OCB   1752    // [i][co]
#define OIOK  1832    // [i][ci][co]
#define OIOB  2408    // [i][co]
#define OMIX  2480    // [i][co]
#define OMIXB 2560
#define NW    2561

__constant__ float Wc[NW];
__device__ float Wstage[NW];

__device__ __forceinline__ uint32_t s2u(const void* p) {
    return (uint32_t)__cvta_generic_to_shared(p);
}
__device__ __forceinline__ uint32_t mapa_peer(uint32_t a, uint32_t peer) {
    uint32_t r;
    asm volatile("mapa.shared::cluster.u32 %0, %1, %2;" : "=r"(r) : "r"(a), "r"(peer));
    return r;
}
__device__ __forceinline__ void st_dsm64(uint32_t a, float x, float y) {
    u64 v = (u64)__float_as_uint(x) | ((u64)__float_as_uint(y) << 32);
    asm volatile("st.shared::cluster.b64 [%0], %1;" :: "r"(a), "l"(v) : "memory");
}
#define CS() do { asm volatile("barrier.cluster.arrive.aligned;" ::: "memory"); \
                  asm volatile("barrier.cluster.wait.aligned;" ::: "memory"); } while(0)

__global__ void pack_weights(const float* __restrict__ c0,  const float* __restrict__ ck,
                             const float* __restrict__ cb,  const float* __restrict__ iok,
                             const float* __restrict__ iob, const float* __restrict__ mix,
                             const float* __restrict__ mixb) {
    int i = blockIdx.x * blockDim.x + threadIdx.x;
    if (i >= NW) return;
    float v;
    if      (i < OCK)   v = c0[i - OC0];
    else if (i < OCB)   v = ck[i - OCK];
    else if (i < OIOK)  v = cb[i - OCB];
    else if (i < OIOB)  v = iok[i - OIOK];
    else if (i < OMIX)  v = iob[i - OIOB];
    else if (i < OMIXB) v = mix[i - OMIX];
    else                v = mixb[0];
    Wstage[i] = v;
}

extern __shared__ float smem[];

__global__ __launch_bounds__(NTH) __cluster_dims__(2, 1, 1)
void wavenet_kernel(const float* __restrict__ X, float* __restrict__ out)
{
    float* xb   = smem;              // LBUF
    float* hA   = smem + LBUF;       // 8*LBUF   h[c*LBUF + l]
    float* hB   = smem + 9 * LBUF;   // 8*LBUF
    float* oacc = smem + 17 * LBUF;  // FRAME

    const int tid = threadIdx.x;
    uint32_t rank;
    asm("mov.u32 %0, %%cluster_ctarank;" : "=r"(rank));
    const uint32_t peer = rank ^ 1u;
    const int b = blockIdx.x >> 1;
    const float* x = X + b * TFULL + (TFULL - LBUF);

    for (int l = tid; l < LBUF; l += NTH) xb[l] = x[l];
    if (rank && tid < FRAME) oacc[tid] = Wc[OMIXB];
    __syncthreads();

    // ---- layer 0 (pairs) -> hA; producer pushes its boundary pair from regs ----
    {
        const int M = 1088;
        const int lo = rank ? M : 2;
        const int hi = rank ? LBUF : M;
        const uint32_t pb = mapa_peer(s2u(hA), peer);
        for (int l = lo + 2 * tid; l < hi; l += 2 * NTH) {
            float2 A = *(const float2*)&xb[l - 2];
            float2 B = *(const float2*)&xb[l];
            float acc0[8], acc1[8];
#pragma unroll
            for (int co = 0; co < 8; co++) {
                float w0 = Wc[OC0 + co], w1 = Wc[OC0 + 8 + co], w2 = Wc[OC0 + 16 + co];
                float bb = Wc[OCB + co];
                acc0[co] = fmaxf(fmaf(B.x, w2, fmaf(A.y, w1, fmaf(A.x, w0, bb))), 0.0f);
                acc1[co] = fmaxf(fmaf(B.y, w2, fmaf(B.x, w1, fmaf(A.y, w0, bb))), 0.0f);
            }
            if (l >= LBUF - FRAME) {
                float m0 = 0.0f, m1 = 0.0f;
#pragma unroll
                for (int co = 0; co < 8; co++) {
                    float mw = Wc[OMIX + co];
                    m0 = fmaf(acc0[co], mw, m0); m1 = fmaf(acc1[co], mw, m1);
                }
                oacc[l - (LBUF - FRAME)]     += m0;
                oacc[l - (LBUF - FRAME) + 1] += m1;
            }
            float o0[8], o1[8];
#pragma unroll
            for (int co = 0; co < 8; co++) {
                float bb = Wc[OIOB + co];
                float a0 = bb + B.x, a1 = bb + B.y;
#pragma unroll
                for (int ci = 0; ci < 8; ci++) {
                    float wk = Wc[OIOK + ci * 8 + co];
                    a0 = fmaf(acc0[ci], wk, a0); a1 = fmaf(acc1[ci], wk, a1);
                }
                o0[co] = a0; o1[co] = a1;
                *(float2*)(hA + co * LBUF + l) = make_float2(a0, a1);
            }
            // layer-1 halo (d=2): rank0 pushes pair 1086, rank1 pushes pair 1088
            if (l == (rank ? 1088 : 1086)) {
#pragma unroll
                for (int co = 0; co < 8; co++)
                    st_dsm64(pb + (uint32_t)(co * LBUF + l) * 4u, o0[co], o1[co]);
            }
        }
    }
    CS();

    // ---- layers 1..8 (pairs), ping-pong, register-tail push halos ----
#pragma unroll
    for (int i = 1; i < 9; i++) {
        const int d = 1 << i;
        const int S = (4 << i) - 2;            // 2*(2^{i+1}-1)
        const int M = 1086 + (2 << i);
        const int W = 2 << i;                  // halo width for layer i+1
        float* cur = (i & 1) ? hA : hB;
        float* nxt = (i & 1) ? hB : hA;
        const uint32_t pb = mapa_peer(s2u(nxt), peer);

        const int lo = rank ? M : S;
        const int hi = rank ? LBUF : M;
        for (int l = lo + 2 * tid; l < hi; l += 2 * NTH) {
            float acc0[8], acc1[8], hl0[8], hl1[8];
#pragma unroll
            for (int co = 0; co < 8; co++) { acc0[co] = Wc[OCB + i * 8 + co]; acc1[co] = acc0[co]; }
#pragma unroll
            for (int w = 0; w < 3; w++) {
                const int off = (2 - w) * d;
#pragma unroll
                for (int ci = 0; ci < 8; ci++) {
                    float2 v = *(const float2*)(cur + ci * LBUF + (l - off));
                    if (w == 2) { hl0[ci] = v.x; hl1[ci] = v.y; }
#pragma unroll
                    for (int co = 0; co < 8; co++) {
                        float wk = Wc[OCK + (((i - 1) * 3 + w) * 8 + ci) * 8 + co];
                        acc0[co] = fmaf(v.x, wk, acc0[co]); acc1[co] = fmaf(v.y, wk, acc1[co]);
                    }
                }
            }
#pragma unroll
            for (int co = 0; co < 8; co++) { acc0[co] = fmaxf(acc0[co], 0.0f); acc1[co] = fmaxf(acc1[co], 0.0f); }
            if (l >= LBUF - FRAME) {
                float m0 = 0.0f, m1 = 0.0f;
#pragma unroll
                for (int co = 0; co < 8; co++) {
                    float mw = Wc[OMIX + i * 8 + co];
                    m0 = fmaf(acc0[co], mw, m0); m1 = fmaf(acc1[co], mw, m1);
                }
                oacc[l - (LBUF - FRAME)]     += m0;
                oacc[l - (LBUF - FRAME) + 1] += m1;
            }
            float o0[8], o1[8];
#pragma unroll
            for (int co = 0; co < 8; co++) {
                float bb = Wc[OIOB + i * 8 + co];
                float a0 = bb + hl0[co], a1 = bb + hl1[co];
#pragma unroll
                for (int ci = 0; ci < 8; ci++) {
                    float wk = Wc[OIOK + (i * 8 + ci) * 8 + co];
                    a0 = fmaf(acc0[ci], wk, a0); a1 = fmaf(acc1[ci], wk, a1);
                }
                o0[co] = a0; o1[co] = a1;
                *(float2*)(nxt + co * LBUF + l) = make_float2(a0, a1);
            }
            // push this pair if it lies in the peer's halo window (producer-owned)
            bool push;
            if (i == 8)   // layer 9 runs on rank1 only; rank0 pushes its strips
                push = rank ? false : ((l >= 1024 && l < 1152) || (l >= 1536 && l < 1598));
            else
                push = rank ? (l >= M && l < M + W) : (l >= M - W && l < M);
            if (push) {
#pragma unroll
                for (int co = 0; co < 8; co++)
                    st_dsm64(pb + (uint32_t)(co * LBUF + l) * 4u, o0[co], o1[co]);
            }
        }
        CS();
    }

    // ---- layer 9 (rank1 only, pairs): reads own hA, last FRAME positions ----
    if (rank) {
        const int i = 9, d = 512;
        for (int l = (LBUF - FRAME) + 2 * tid; l < LBUF; l += 2 * NTH) {
            float acc0[8], acc1[8];
#pragma unroll
            for (int co = 0; co < 8; co++) { acc0[co] = Wc[OCB + i * 8 + co]; acc1[co] = acc0[co]; }
#pragma unroll
            for (int w = 0; w < 3; w++) {
                const int off = (2 - w) * d;
#pragma unroll
                for (int ci = 0; ci < 8; ci++) {
                    float2 v = *(const float2*)(hA + ci * LBUF + (l - off));
#pragma unroll
                    for (int co = 0; co < 8; co++) {
                        float wk = Wc[OCK + (((i - 1) * 3 + w) * 8 + ci) * 8 + co];
                        acc0[co] = fmaf(v.x, wk, acc0[co]); acc1[co] = fmaf(v.y, wk, acc1[co]);
                    }
                }
            }
            float m0 = 0.0f, m1 = 0.0f;
#pragma unroll
            for (int co = 0; co < 8; co++) {
                float mw = Wc[OMIX + i * 8 + co];
                m0 = fmaf(fmaxf(acc0[co], 0.0f), mw, m0);
                m1 = fmaf(fmaxf(acc1[co], 0.0f), mw, m1);
            }
            oacc[l - (LBUF - FRAME)]     += m0;
            oacc[l - (LBUF - FRAME) + 1] += m1;
        }
        __syncthreads();
        if (tid < FRAME) out[b * FRAME + tid] = oacc[tid];
    }
}

static const int SMEM_BYTES = (17 * LBUF + FRAME) * (int)sizeof(float);

extern "C" void kernel_launch(void* const* d_in, const int* in_sizes, int n_in,
                              void* d_out, int out_size) {
    (void)in_sizes; (void)n_in; (void)out_size;
    cudaFuncSetAttribute(wavenet_kernel, cudaFuncAttributeMaxDynamicSharedMemorySize, SMEM_BYTES);

    pack_weights<<<(NW + 511) / 512, 512>>>(
        (const float*)d_in[1], (const float*)d_in[2], (const float*)d_in[3],
        (const float*)d_in[4], (const float*)d_in[5], (const float*)d_in[6],
        (const float*)d_in[7]);

    void* wp = nullptr;
    cudaGetSymbolAddress(&wp, Wstage);
    cudaMemcpyToSymbolAsync(Wc, wp, NW * sizeof(float), 0, cudaMemcpyDeviceToDevice, 0);

    wavenet_kernel<<<128, NTH, SMEM_BYTES>>>((const float*)d_in[0], (float*)d_out);
}